// round 1
// baseline (speedup 1.0000x reference)
#include <cuda_runtime.h>

#define EPS 1e-5f

// ---------------- scratch (device globals; no allocation allowed) ----------------
__device__ float g_xn[4 * 144 * 4096];        // normalized input
__device__ float g_wint[144 * 64];            // w_in transposed [c][o]
__device__ float g_w1t[576 * 64];             // w1 as [(o*9+drds)][o2]
__device__ float g_w2rt[576 * 64];            // w2 as [(rs*64+o2)][o3]
__device__ float g_sin[64], g_tin[64];
__device__ float g_s1[64],  g_t1[64];
__device__ float g_s2[64],  g_t2[64];
__device__ float g_sout[144], g_tout[144];
__device__ float g_A[16384 * 25 * 64];        // post GEMM1+BN+ReLU  [pos][k][o]
__device__ float g_A1[16384 * 9 * 64];        // post conv1+BN+ReLU  [pos][rs][o2]
__device__ float g_B2[16384 * 64];            // post conv2+BN+ReLU  [pos][o3]

// ---------------- weight transpose + BN folding ----------------
__global__ void prep_kernel(const float* __restrict__ w_in,
                            const float* __restrict__ gin, const float* __restrict__ bin,
                            const float* __restrict__ min_, const float* __restrict__ vin,
                            const float* __restrict__ w1,
                            const float* __restrict__ g1, const float* __restrict__ b1,
                            const float* __restrict__ m1, const float* __restrict__ v1,
                            const float* __restrict__ w2,
                            const float* __restrict__ g2, const float* __restrict__ b2,
                            const float* __restrict__ m2, const float* __restrict__ v2,
                            const float* __restrict__ w_out,
                            const float* __restrict__ go, const float* __restrict__ bo,
                            const float* __restrict__ mo, const float* __restrict__ vo)
{
    int i = blockIdx.x * blockDim.x + threadIdx.x;   // grid covers 36864
    if (i < 36864) {
        // w1t[(o*9+drds)*64 + o2] = w1[o2][o][drds]
        int o = i / 576; int rem = i - o * 576;
        int drds = rem >> 6; int o2 = rem & 63;
        g_w1t[i] = w1[(o2 * 64 + o) * 9 + drds];
        // w2rt[(rs*64+o2)*64 + o3] = w2[o3][o2][rs]
        int rs = i >> 12; int rem2 = i & 4095;
        int o2b = rem2 >> 6; int o3 = rem2 & 63;
        g_w2rt[i] = w2[(o3 * 64 + o2b) * 9 + rs];
    }
    if (i < 9216) { int c = i >> 6; int o = i & 63; g_wint[i] = w_in[o * 144 + c]; }
    if (i < 64) {
        float s;
        s = gin[i] * rsqrtf(vin[i] + EPS); g_sin[i] = s; g_tin[i] = bin[i] - min_[i] * s;
        s = g1[i]  * rsqrtf(v1[i]  + EPS); g_s1[i]  = s; g_t1[i]  = b1[i]  - m1[i]  * s;
        s = g2[i]  * rsqrtf(v2[i]  + EPS); g_s2[i]  = s; g_t2[i]  = b2[i]  - m2[i]  * s;
    }
    if (i < 144) {
        float s = go[i] * rsqrtf(vo[i] + EPS); g_sout[i] = s; g_tout[i] = bo[i] - mo[i] * s;
    }
    (void)w_out;
}

// ---------------- L2 normalize over channels ----------------
__global__ void normalize_kernel(const float* __restrict__ x)
{
    int p = blockIdx.x * 256 + threadIdx.x;          // 16384 positions
    int b = p >> 12, hw = p & 4095;
    const float* xb = x + (size_t)b * 589824 + hw;   // 144*4096
    float ss = 0.f;
    #pragma unroll 4
    for (int c = 0; c < 144; c++) { float v = xb[c * 4096]; ss += v * v; }
    float inv = 1.0f / fmaxf(sqrtf(ss), 1e-12f);
    float* yb = g_xn + (size_t)b * 589824 + hw;
    #pragma unroll 4
    for (int c = 0; c < 144; c++) yb[c * 4096] = xb[c * 4096] * inv;
}

// ---------------- GEMM1: z[o,k,p] = sum_c w_in[o,c] * y[c,k,p]; BN+ReLU ----------------
// CTA = 8 consecutive positions (one row segment). smem y[144][25*8].
__global__ void __launch_bounds__(256) gemm1_kernel()
{
    extern __shared__ float y[];                     // 144*200 floats = 115.2KB
    int pos0 = blockIdx.x << 3;
    int b = pos0 >> 12, hw0 = pos0 & 4095;
    int h = hw0 >> 6, w0 = hw0 & 63;
    int tid = threadIdx.x;
    const float* xb = g_xn + (size_t)b * 589824;

    for (int idx = tid; idx < 28800; idx += 256) {
        int c = idx / 200; int rem = idx - c * 200;
        int k = rem >> 3, p = rem & 7;
        int kh = k / 5, kw = k - kh * 5;
        int gh = h + kh - 2, gw = w0 + p + kw - 2;
        float v = 0.f;
        if ((unsigned)gh < 64u && (unsigned)gw < 64u) v = xb[c * 4096 + (gh << 6) + gw];
        y[idx] = v * xb[c * 4096 + (h << 6) + w0 + p];
    }
    __syncthreads();

    int ob = tid & 31, g = tid >> 5;                 // o in {ob, ob+32}; warp g owns k = g, g+8, g+16 (+24 for g=0)
    int nk = (g == 0) ? 4 : 3;
    float acc[4][2][8];
    #pragma unroll
    for (int kk = 0; kk < 4; kk++)
        #pragma unroll
        for (int p = 0; p < 8; p++) { acc[kk][0][p] = 0.f; acc[kk][1][p] = 0.f; }

    for (int c = 0; c < 144; c++) {
        float wa = g_wint[(c << 6) + ob];
        float wb = g_wint[(c << 6) + ob + 32];
        const float4* yr = (const float4*)(y + c * 200);
        #pragma unroll
        for (int kk = 0; kk < 4; kk++) {
            if (kk < nk) {
                int k2 = (g + (kk << 3)) * 2;
                float4 y0 = yr[k2], y1 = yr[k2 + 1];
                float yv[8] = {y0.x, y0.y, y0.z, y0.w, y1.x, y1.y, y1.z, y1.w};
                #pragma unroll
                for (int p = 0; p < 8; p++) {
                    acc[kk][0][p] += wa * yv[p];
                    acc[kk][1][p] += wb * yv[p];
                }
            }
        }
    }

    float sa = g_sin[ob], ta = g_tin[ob], sb = g_sin[ob + 32], tb = g_tin[ob + 32];
    #pragma unroll
    for (int kk = 0; kk < 4; kk++) {
        if (kk < nk) {
            int k = g + (kk << 3);
            #pragma unroll
            for (int p = 0; p < 8; p++) {
                int base = (((pos0 + p) * 25) + k) << 6;
                g_A[base + ob]      = fmaxf(acc[kk][0][p] * sa + ta, 0.f);
                g_A[base + ob + 32] = fmaxf(acc[kk][1][p] * sb + tb, 0.f);
            }
        }
    }
}

// ---------------- Conv1: 3x3 VALID over 5x5 grid, 64->64; BN+ReLU ----------------
// CTA = 8 positions. smem A tile [8][25][64] = 51.2KB.
__global__ void __launch_bounds__(256) conv1_kernel()
{
    extern __shared__ float4 As4[];                  // 3200 float4
    int pos0 = blockIdx.x << 3;
    int tid = threadIdx.x;
    const float4* Ag = (const float4*)(g_A + ((size_t)pos0 * 1600));
    for (int i = tid; i < 3200; i += 256) As4[i] = Ag[i];
    __syncthreads();

    int o2b = tid & 31, g = tid >> 5;                // warp g owns 9 of 72 (rs,p) outputs
    int rr[9], ss_[9], pp[9];
    #pragma unroll
    for (int i = 0; i < 9; i++) {
        int pid = g * 9 + i;
        int rs = pid >> 3; pp[i] = pid & 7;
        rr[i] = rs / 3; ss_[i] = rs - rr[i] * 3;
    }
    float acc[9][2];
    #pragma unroll
    for (int i = 0; i < 9; i++) { acc[i][0] = 0.f; acc[i][1] = 0.f; }

    for (int dr = 0; dr < 3; dr++)
    for (int ds = 0; ds < 3; ds++) {
        int drds = dr * 3 + ds;
        int base[9];
        #pragma unroll
        for (int i = 0; i < 9; i++)
            base[i] = (pp[i] * 25 + (rr[i] + dr) * 5 + ss_[i] + ds) << 4;   // float4 units
        const float* wr = g_w1t + (drds << 6) + o2b;
        for (int o4 = 0; o4 < 16; o4++) {
            float wA[4], wB[4];
            #pragma unroll
            for (int oo = 0; oo < 4; oo++) {
                int o = o4 * 4 + oo;
                wA[oo] = wr[o * 576];
                wB[oo] = wr[o * 576 + 32];
            }
            #pragma unroll
            for (int i = 0; i < 9; i++) {
                float4 a = As4[base[i] + o4];
                float av[4] = {a.x, a.y, a.z, a.w};
                #pragma unroll
                for (int oo = 0; oo < 4; oo++) {
                    acc[i][0] += wA[oo] * av[oo];
                    acc[i][1] += wB[oo] * av[oo];
                }
            }
        }
    }

    float sa = g_s1[o2b], ta = g_t1[o2b], sb = g_s1[o2b + 32], tb = g_t1[o2b + 32];
    #pragma unroll
    for (int i = 0; i < 9; i++) {
        int rs = rr[i] * 3 + ss_[i];
        int base = (((pos0 + pp[i]) * 9) + rs) << 6;
        g_A1[base + o2b]      = fmaxf(acc[i][0] * sa + ta, 0.f);
        g_A1[base + o2b + 32] = fmaxf(acc[i][1] * sb + tb, 0.f);
    }
}

// ---------------- Conv2: 3x3 -> 1x1, 64->64; BN+ReLU ----------------
// CTA = 32 positions. smem A1 tile [32][576] = 73.7KB.
__global__ void __launch_bounds__(256) conv2_kernel()
{
    extern __shared__ float4 A1s4[];                 // 4608 float4
    int pos0 = blockIdx.x << 5;
    int tid = threadIdx.x;
    const float4* src = (const float4*)(g_A1 + ((size_t)pos0 * 576));
    for (int i = tid; i < 4608; i += 256) A1s4[i] = src[i];
    __syncthreads();

    int o3b = tid & 31, g = tid >> 5;                // warp g owns p = g, g+8, g+16, g+24
    float acc[4][2];
    #pragma unroll
    for (int i = 0; i < 4; i++) { acc[i][0] = 0.f; acc[i][1] = 0.f; }

    for (int j4 = 0; j4 < 144; j4++) {
        const float* wr = g_w2rt + (j4 << 8) + o3b;
        float wA[4], wB[4];
        #pragma unroll
        for (int jj = 0; jj < 4; jj++) {
            wA[jj] = wr[jj * 64];
            wB[jj] = wr[jj * 64 + 32];
        }
        #pragma unroll
        for (int i = 0; i < 4; i++) {
            int p = g + (i << 3);
            float4 a = A1s4[p * 144 + j4];
            float av[4] = {a.x, a.y, a.z, a.w};
            #pragma unroll
            for (int jj = 0; jj < 4; jj++) {
                acc[i][0] += wA[jj] * av[jj];
                acc[i][1] += wB[jj] * av[jj];
            }
        }
    }

    float sa = g_s2[o3b], ta = g_t2[o3b], sb = g_s2[o3b + 32], tb = g_t2[o3b + 32];
    #pragma unroll
    for (int i = 0; i < 4; i++) {
        int p = pos0 + g + (i << 3);
        g_B2[(p << 6) + o3b]      = fmaxf(acc[i][0] * sa + ta, 0.f);
        g_B2[(p << 6) + o3b + 32] = fmaxf(acc[i][1] * sb + tb, 0.f);
    }
}

// ---------------- GEMM out: 64->144, BN (no ReLU) ----------------
// CTA = 64 positions (one full h-row). smem: B2 transposed [64][65] + w staged.
__global__ void __launch_bounds__(256) gemmout_kernel(const float* __restrict__ w_out,
                                                      float* __restrict__ out)
{
    extern __shared__ float sm[];                    // 4160 + 9216 floats
    float* B2t = sm;
    float* ws  = sm + 4160;
    int pos0 = blockIdx.x << 6;
    int tid = threadIdx.x;

    for (int idx = tid; idx < 4096; idx += 256) {
        int p = idx >> 6, cm = idx & 63;
        B2t[cm * 65 + p] = g_B2[(pos0 << 6) + idx];
    }
    for (int idx = tid; idx < 9216; idx += 256) {
        int cm = idx / 144; int rm = idx - cm * 144;
        int ocg = rm / 36;  int i  = rm - ocg * 36;
        ws[idx] = w_out[((ocg + (i << 2)) << 6) + cm];   // oc = ocg + 4*i
    }
    __syncthreads();

    int pl = tid & 63, ocg = tid >> 6;
    float acc[36];
    #pragma unroll
    for (int i = 0; i < 36; i++) acc[i] = 0.f;

    for (int cm = 0; cm < 64; cm++) {
        float bv = B2t[cm * 65 + pl];
        const float4* wp = (const float4*)(ws + cm * 144 + ocg * 36);
        #pragma unroll
        for (int i4 = 0; i4 < 9; i4++) {
            float4 w = wp[i4];
            acc[i4 * 4 + 0] += w.x * bv;
            acc[i4 * 4 + 1] += w.y * bv;
            acc[i4 * 4 + 2] += w.z * bv;
            acc[i4 * 4 + 3] += w.w * bv;
        }
    }

    int b = pos0 >> 12, hw0 = pos0 & 4095;
    float* op = out + (size_t)b * 589824 + hw0 + pl;
    #pragma unroll
    for (int i = 0; i < 36; i++) {
        int oc = ocg + (i << 2);
        op[oc * 4096] = acc[i] * g_sout[oc] + g_tout[oc];
    }
}

// ---------------- launch ----------------
extern "C" void kernel_launch(void* const* d_in, const int* in_sizes, int n_in,
                              void* d_out, int out_size)
{
    (void)in_sizes; (void)n_in; (void)out_size;
    const float* x     = (const float*)d_in[0];
    const float* w_in  = (const float*)d_in[1];
    const float* gin   = (const float*)d_in[2];
    const float* bin   = (const float*)d_in[3];
    const float* min_  = (const float*)d_in[4];
    const float* vin   = (const float*)d_in[5];
    const float* w1    = (const float*)d_in[6];
    const float* g1    = (const float*)d_in[7];
    const float* b1    = (const float*)d_in[8];
    const float* m1    = (const float*)d_in[9];
    const float* v1    = (const float*)d_in[10];
    const float* w2    = (const float*)d_in[11];
    const float* g2    = (const float*)d_in[12];
    const float* b2    = (const float*)d_in[13];
    const float* m2    = (const float*)d_in[14];
    const float* v2    = (const float*)d_in[15];
    const float* w_out = (const float*)d_in[16];
    const float* go    = (const float*)d_in[17];
    const float* bo    = (const float*)d_in[18];
    const float* mo    = (const float*)d_in[19];
    const float* vo    = (const float*)d_in[20];
    float* out = (float*)d_out;

    cudaFuncSetAttribute(gemm1_kernel,  cudaFuncAttributeMaxDynamicSharedMemorySize, 115200);
    cudaFuncSetAttribute(conv1_kernel,  cudaFuncAttributeMaxDynamicSharedMemorySize, 51200);
    cudaFuncSetAttribute(conv2_kernel,  cudaFuncAttributeMaxDynamicSharedMemorySize, 73728);
    cudaFuncSetAttribute(gemmout_kernel, cudaFuncAttributeMaxDynamicSharedMemorySize, 53504);

    prep_kernel<<<144, 256>>>(w_in, gin, bin, min_, vin,
                              w1, g1, b1, m1, v1,
                              w2, g2, b2, m2, v2,
                              w_out, go, bo, mo, vo);
    normalize_kernel<<<64, 256>>>(x);
    gemm1_kernel<<<2048, 256, 115200>>>();
    conv1_kernel<<<2048, 256, 51200>>>();
    conv2_kernel<<<512, 256, 73728>>>();
    gemmout_kernel<<<256, 256, 53504>>>(w_out, out);
}

// round 2
// speedup vs baseline: 1.5678x; 1.5678x over previous
#include <cuda_runtime.h>

#define EPS 1e-5f

typedef unsigned long long u64;

// ---------------- f32x2 helpers ----------------
__device__ __forceinline__ void fma2(u64& d, u64 a, u64 b) {
    asm volatile("fma.rn.f32x2 %0, %1, %2, %0;" : "+l"(d) : "l"(a), "l"(b));
}
__device__ __forceinline__ u64 dup2(float x) {
    u64 r; asm("mov.b64 %0, {%1, %1};" : "=l"(r) : "f"(x)); return r;
}
__device__ __forceinline__ float2 unpack2(u64 v) {
    float2 r; asm("mov.b64 {%0, %1}, %2;" : "=f"(r.x), "=f"(r.y) : "l"(v)); return r;
}

// ---------------- scratch (device globals; no allocation allowed) ----------------
__device__ float g_xn[4 * 144 * 4096];        // normalized input
__device__ float g_wint[144 * 64];            // w_in transposed [c][o]
__device__ float g_w1tt[9 * 64 * 64];         // w1 as [drds][o2][o]
__device__ float g_w2tt[64 * 576];            // w2 as [o3][rs*64+o2]
__device__ float g_sin[64], g_tin[64];
__device__ float g_s1[64],  g_t1[64];
__device__ float g_s2[64],  g_t2[64];
__device__ float g_sout[144], g_tout[144];
__device__ float g_A[16384 * 25 * 64];        // post GEMM1+BN+ReLU  [pos][k][o]
__device__ float g_A1[16384 * 9 * 64];        // post conv1+BN+ReLU  [pos][rs][o2]
__device__ float g_B2[16384 * 64];            // post conv2+BN+ReLU  [pos][o3]

// ---------------- weight transpose + BN folding ----------------
__global__ void prep_kernel(const float* __restrict__ w_in,
                            const float* __restrict__ gin, const float* __restrict__ bin,
                            const float* __restrict__ min_, const float* __restrict__ vin,
                            const float* __restrict__ w1,
                            const float* __restrict__ g1, const float* __restrict__ b1,
                            const float* __restrict__ m1, const float* __restrict__ v1,
                            const float* __restrict__ w2,
                            const float* __restrict__ g2, const float* __restrict__ b2,
                            const float* __restrict__ m2, const float* __restrict__ v2,
                            const float* __restrict__ go, const float* __restrict__ bo,
                            const float* __restrict__ mo, const float* __restrict__ vo)
{
    int i = blockIdx.x * blockDim.x + threadIdx.x;   // grid covers 36864
    if (i < 36864) {
        // w1tt[drds][o2][o] = w1[o2][o][drds]
        int drds = i >> 12; int r1 = i & 4095;
        int o2 = r1 >> 6; int o = r1 & 63;
        g_w1tt[i] = w1[(o2 * 64 + o) * 9 + drds];
        // w2tt[o3][rs*64+o2] = w2[o3][o2][rs]
        int o3 = i / 576; int r2 = i - o3 * 576;
        int rs = r2 >> 6; int o2b = r2 & 63;
        g_w2tt[i] = w2[(o3 * 64 + o2b) * 9 + rs];
    }
    if (i < 9216) { int c = i >> 6; int o = i & 63; g_wint[i] = w_in[o * 144 + c]; }
    if (i < 64) {
        float s;
        s = gin[i] * rsqrtf(vin[i] + EPS); g_sin[i] = s; g_tin[i] = bin[i] - min_[i] * s;
        s = g1[i]  * rsqrtf(v1[i]  + EPS); g_s1[i]  = s; g_t1[i]  = b1[i]  - m1[i]  * s;
        s = g2[i]  * rsqrtf(v2[i]  + EPS); g_s2[i]  = s; g_t2[i]  = b2[i]  - m2[i]  * s;
    }
    if (i < 144) {
        float s = go[i] * rsqrtf(vo[i] + EPS); g_sout[i] = s; g_tout[i] = bo[i] - mo[i] * s;
    }
}

// ---------------- L2 normalize over channels ----------------
__global__ void normalize_kernel(const float* __restrict__ x)
{
    int p = blockIdx.x * 256 + threadIdx.x;          // 16384 positions
    int b = p >> 12, hw = p & 4095;
    const float* xb = x + (size_t)b * 589824 + hw;   // 144*4096
    float ss = 0.f;
    #pragma unroll 4
    for (int c = 0; c < 144; c++) { float v = xb[c * 4096]; ss += v * v; }
    float inv = 1.0f / fmaxf(sqrtf(ss), 1e-12f);
    float* yb = g_xn + (size_t)b * 589824 + hw;
    #pragma unroll 4
    for (int c = 0; c < 144; c++) yb[c * 4096] = xb[c * 4096] * inv;
}

// ---------------- GEMM1: z[p,k,o] = sum_c w_in[o,c]*y[c,k,p]; BN+ReLU ----------------
// CTA = 4 positions. smem: y[144][25][4] (57.6KB) + wint[144][64] (36.8KB) -> 2 CTA/SM.
// f32x2 packed along p: acc covers (p0,p1),(p2,p3).
__global__ void __launch_bounds__(256) gemm1_kernel()
{
    extern __shared__ float sm[];
    float* y   = sm;                                 // 14400
    float* wsm = sm + 14400;                         // 9216
    int pos0 = blockIdx.x << 2;
    int b = pos0 >> 12, hw0 = pos0 & 4095;
    int h = hw0 >> 6, w0 = hw0 & 63;
    int tid = threadIdx.x;
    const float* xb = g_xn + (size_t)b * 589824;

    // stage w_in^T
    #pragma unroll
    for (int j = 0; j < 9; j++) {
        int idx = tid + j * 256;                     // 2304 float4 = 9216 floats
        ((float4*)wsm)[idx] = ((const float4*)g_wint)[idx];
    }
    // build y tile: y[(c*25+k)*4 + p] = patch(c,k,p) * center(c,p)
    for (int u = tid; u < 3600; u += 256) {
        int c = u / 25, k = u - c * 25;
        int kh = k / 5, kw = k - kh * 5;
        int gh = h + kh - 2;
        bool rok = ((unsigned)gh < 64u);
        const float* xc = xb + c * 4096;
        float4 out;
        float ctr0 = xc[(h << 6) + w0 + 0], ctr1 = xc[(h << 6) + w0 + 1];
        float ctr2 = xc[(h << 6) + w0 + 2], ctr3 = xc[(h << 6) + w0 + 3];
        int gw0 = w0 + kw - 2;
        float v0 = (rok && (unsigned)(gw0 + 0) < 64u) ? xc[(gh << 6) + gw0 + 0] : 0.f;
        float v1 = (rok && (unsigned)(gw0 + 1) < 64u) ? xc[(gh << 6) + gw0 + 1] : 0.f;
        float v2 = (rok && (unsigned)(gw0 + 2) < 64u) ? xc[(gh << 6) + gw0 + 2] : 0.f;
        float v3 = (rok && (unsigned)(gw0 + 3) < 64u) ? xc[(gh << 6) + gw0 + 3] : 0.f;
        out.x = v0 * ctr0; out.y = v1 * ctr1; out.z = v2 * ctr2; out.w = v3 * ctr3;
        ((float4*)y)[u] = out;
    }
    __syncthreads();

    int ob = tid & 31, g = tid >> 5;                 // o in {ob, ob+32}; warp g: k = g+8j
    int nk = (g == 0) ? 4 : 3;
    u64 acc[4][2][2];
    #pragma unroll
    for (int kk = 0; kk < 4; kk++) { acc[kk][0][0]=0; acc[kk][0][1]=0; acc[kk][1][0]=0; acc[kk][1][1]=0; }

    for (int c = 0; c < 144; c++) {
        u64 wa2 = dup2(wsm[(c << 6) + ob]);
        u64 wb2 = dup2(wsm[(c << 6) + ob + 32]);
        #pragma unroll
        for (int kk = 0; kk < 4; kk++) {
            if (kk < nk) {
                int k = g + (kk << 3);
                ulonglong2 yv = *(const ulonglong2*)&y[(c * 25 + k) << 2];
                fma2(acc[kk][0][0], yv.x, wa2);
                fma2(acc[kk][0][1], yv.y, wa2);
                fma2(acc[kk][1][0], yv.x, wb2);
                fma2(acc[kk][1][1], yv.y, wb2);
            }
        }
    }

    float sa = g_sin[ob], ta = g_tin[ob], sb = g_sin[ob + 32], tb = g_tin[ob + 32];
    #pragma unroll
    for (int kk = 0; kk < 4; kk++) {
        if (kk < nk) {
            int k = g + (kk << 3);
            #pragma unroll
            for (int pp = 0; pp < 2; pp++) {
                float2 va = unpack2(acc[kk][0][pp]);
                float2 vb = unpack2(acc[kk][1][pp]);
                int base0 = (((pos0 + 2 * pp)     * 25) + k) << 6;
                int base1 = (((pos0 + 2 * pp + 1) * 25) + k) << 6;
                g_A[base0 + ob]      = fmaxf(va.x * sa + ta, 0.f);
                g_A[base1 + ob]      = fmaxf(va.y * sa + ta, 0.f);
                g_A[base0 + ob + 32] = fmaxf(vb.x * sb + tb, 0.f);
                g_A[base1 + ob + 32] = fmaxf(vb.y * sb + tb, 0.f);
            }
        }
    }
}

// ---------------- Conv1: 3x3 VALID over 5x5 grid, 64->64; BN+ReLU ----------------
// CTA = 8 positions. smem: A[8][25][64] (51.2KB) + w slice [64][66] (16.9KB) -> 3 CTA/SM.
// f32x2 packed along contraction o; per-drds weight staging.
__global__ void __launch_bounds__(256) conv1_kernel()
{
    extern __shared__ float sm[];
    float* As  = sm;                                 // 12800
    float* ws1 = sm + 12800;                         // 64*66 = 4224
    int pos0 = blockIdx.x << 3;
    int tid = threadIdx.x;

    const float4* Ag = (const float4*)(g_A + ((size_t)pos0 * 1600));
    for (int i = tid; i < 3200; i += 256) ((float4*)As)[i] = Ag[i];

    int o2b = tid & 31, g = tid >> 5;                // warp g owns 9 of 72 (rs,p) units
    int roff[9], pp[9];                              // patch row base (r*5+s), pos
    #pragma unroll
    for (int i = 0; i < 9; i++) {
        int pid = g * 9 + i;
        int rs = pid >> 3; pp[i] = pid & 7;
        int r = rs / 3, s = rs - r * 3;
        roff[i] = r * 5 + s;
    }
    u64 acc[9][2];
    #pragma unroll
    for (int i = 0; i < 9; i++) { acc[i][0] = 0; acc[i][1] = 0; }

    for (int drds = 0; drds < 9; drds++) {
        // stage w slice [o2][o] padded to 66
        const float* wsrc = g_w1tt + (drds << 12);
        #pragma unroll
        for (int j = 0; j < 16; j++) {
            int idx = tid + (j << 8);
            int o2 = idx >> 6, o = idx & 63;
            ws1[o2 * 66 + o] = wsrc[idx];
        }
        __syncthreads();

        int dr = drds / 3, ds = drds - dr * 3;
        int shift = dr * 5 + ds;
        int base[9];
        #pragma unroll
        for (int i = 0; i < 9; i++)
            base[i] = (pp[i] * 25 + roff[i] + shift) << 6;

        const float* wlo_p = ws1 + o2b * 66;
        const float* whi_p = ws1 + (o2b + 32) * 66;
        #pragma unroll 4
        for (int o = 0; o < 64; o += 2) {
            u64 wlo = *(const u64*)(wlo_p + o);
            u64 whi = *(const u64*)(whi_p + o);
            #pragma unroll
            for (int i = 0; i < 9; i++) {
                u64 a = *(const u64*)&As[base[i] + o];
                fma2(acc[i][0], a, wlo);
                fma2(acc[i][1], a, whi);
            }
        }
        __syncthreads();
    }

    float sa = g_s1[o2b], ta = g_t1[o2b], sb = g_s1[o2b + 32], tb = g_t1[o2b + 32];
    #pragma unroll
    for (int i = 0; i < 9; i++) {
        int pid = g * 9 + i;
        int rs = pid >> 3;
        float2 va = unpack2(acc[i][0]);
        float2 vb = unpack2(acc[i][1]);
        int base = (((pos0 + pp[i]) * 9) + rs) << 6;
        g_A1[base + o2b]      = fmaxf((va.x + va.y) * sa + ta, 0.f);
        g_A1[base + o2b + 32] = fmaxf((vb.x + vb.y) * sb + tb, 0.f);
    }
}

// ---------------- Conv2: 3x3 -> 1x1, 64->64; BN+ReLU ----------------
// CTA = 32 positions. smem: A1[32][576] (73.7KB) + w chunk [64][66] (16.9KB) -> 2 CTA/SM.
// f32x2 packed along contraction j = rs*64+o2; chunked weight staging (9 x 64).
__global__ void __launch_bounds__(256) conv2_kernel()
{
    extern __shared__ float sm[];
    float* A1s = sm;                                 // 18432
    float* ws2 = sm + 18432;                         // 4224
    int pos0 = blockIdx.x << 5;
    int tid = threadIdx.x;

    const float4* src = (const float4*)(g_A1 + ((size_t)pos0 * 576));
    for (int i = tid; i < 4608; i += 256) ((float4*)A1s)[i] = src[i];

    int o3b = tid & 31, g = tid >> 5;                // warp g owns p = g+8i
    u64 acc[4][2];
    #pragma unroll
    for (int i = 0; i < 4; i++) { acc[i][0] = 0; acc[i][1] = 0; }

    for (int jc = 0; jc < 9; jc++) {
        #pragma unroll
        for (int j = 0; j < 16; j++) {
            int idx = tid + (j << 8);
            int o3 = idx >> 6, jj = idx & 63;
            ws2[o3 * 66 + jj] = g_w2tt[o3 * 576 + (jc << 6) + jj];
        }
        __syncthreads();

        const float* wlo_p = ws2 + o3b * 66;
        const float* whi_p = ws2 + (o3b + 32) * 66;
        int jbase = jc << 6;
        #pragma unroll 4
        for (int jj = 0; jj < 64; jj += 2) {
            u64 wlo = *(const u64*)(wlo_p + jj);
            u64 whi = *(const u64*)(whi_p + jj);
            #pragma unroll
            for (int i = 0; i < 4; i++) {
                int p = g + (i << 3);
                u64 a = *(const u64*)&A1s[p * 576 + jbase + jj];
                fma2(acc[i][0], a, wlo);
                fma2(acc[i][1], a, whi);
            }
        }
        __syncthreads();
    }

    float sa = g_s2[o3b], ta = g_t2[o3b], sb = g_s2[o3b + 32], tb = g_t2[o3b + 32];
    #pragma unroll
    for (int i = 0; i < 4; i++) {
        int p = pos0 + g + (i << 3);
        float2 va = unpack2(acc[i][0]);
        float2 vb = unpack2(acc[i][1]);
        g_B2[(p << 6) + o3b]      = fmaxf((va.x + va.y) * sa + ta, 0.f);
        g_B2[(p << 6) + o3b + 32] = fmaxf((vb.x + vb.y) * sb + tb, 0.f);
    }
}

// ---------------- GEMM out: 64->144, BN (no ReLU) ----------------
// CTA = 64 positions (one full h-row). smem: B2 transposed [64][65] + w staged.
__global__ void __launch_bounds__(256) gemmout_kernel(const float* __restrict__ w_out,
                                                      float* __restrict__ out)
{
    extern __shared__ float sm[];                    // 4160 + 9216 floats
    float* B2t = sm;
    float* ws  = sm + 4160;
    int pos0 = blockIdx.x << 6;
    int tid = threadIdx.x;

    for (int idx = tid; idx < 4096; idx += 256) {
        int p = idx >> 6, cm = idx & 63;
        B2t[cm * 65 + p] = g_B2[(pos0 << 6) + idx];
    }
    for (int idx = tid; idx < 9216; idx += 256) {
        int cm = idx / 144; int rm = idx - cm * 144;
        int ocg = rm / 36;  int i  = rm - ocg * 36;
        ws[idx] = w_out[((ocg + (i << 2)) << 6) + cm];   // oc = ocg + 4*i
    }
    __syncthreads();

    int pl = tid & 63, ocg = tid >> 6;
    float acc[36];
    #pragma unroll
    for (int i = 0; i < 36; i++) acc[i] = 0.f;

    for (int cm = 0; cm < 64; cm++) {
        float bv = B2t[cm * 65 + pl];
        const float4* wp = (const float4*)(ws + cm * 144 + ocg * 36);
        #pragma unroll
        for (int i4 = 0; i4 < 9; i4++) {
            float4 w = wp[i4];
            acc[i4 * 4 + 0] += w.x * bv;
            acc[i4 * 4 + 1] += w.y * bv;
            acc[i4 * 4 + 2] += w.z * bv;
            acc[i4 * 4 + 3] += w.w * bv;
        }
    }

    int b = pos0 >> 12, hw0 = pos0 & 4095;
    float* op = out + (size_t)b * 589824 + hw0 + pl;
    #pragma unroll
    for (int i = 0; i < 36; i++) {
        int oc = ocg + (i << 2);
        op[oc * 4096] = acc[i] * g_sout[oc] + g_tout[oc];
    }
}

// ---------------- launch ----------------
extern "C" void kernel_launch(void* const* d_in, const int* in_sizes, int n_in,
                              void* d_out, int out_size)
{
    (void)in_sizes; (void)n_in; (void)out_size;
    const float* x     = (const float*)d_in[0];
    const float* w_in  = (const float*)d_in[1];
    const float* gin   = (const float*)d_in[2];
    const float* bin   = (const float*)d_in[3];
    const float* min_  = (const float*)d_in[4];
    const float* vin   = (const float*)d_in[5];
    const float* w1    = (const float*)d_in[6];
    const float* g1    = (const float*)d_in[7];
    const float* b1    = (const float*)d_in[8];
    const float* m1    = (const float*)d_in[9];
    const float* v1    = (const float*)d_in[10];
    const float* w2    = (const float*)d_in[11];
    const float* g2    = (const float*)d_in[12];
    const float* b2    = (const float*)d_in[13];
    const float* m2    = (const float*)d_in[14];
    const float* v2    = (const float*)d_in[15];
    const float* w_out = (const float*)d_in[16];
    const float* go    = (const float*)d_in[17];
    const float* bo    = (const float*)d_in[18];
    const float* mo    = (const float*)d_in[19];
    const float* vo    = (const float*)d_in[20];
    float* out = (float*)d_out;

    cudaFuncSetAttribute(gemm1_kernel,   cudaFuncAttributeMaxDynamicSharedMemorySize, 94464);
    cudaFuncSetAttribute(conv1_kernel,   cudaFuncAttributeMaxDynamicSharedMemorySize, 68096);
    cudaFuncSetAttribute(conv2_kernel,   cudaFuncAttributeMaxDynamicSharedMemorySize, 90624);
    cudaFuncSetAttribute(gemmout_kernel, cudaFuncAttributeMaxDynamicSharedMemorySize, 53504);

    prep_kernel<<<144, 256>>>(w_in, gin, bin, min_, vin,
                              w1, g1, b1, m1, v1,
                              w2, g2, b2, m2, v2,
                              go, bo, mo, vo);
    normalize_kernel<<<64, 256>>>(x);
    gemm1_kernel<<<4096, 256, 94464>>>();
    conv1_kernel<<<2048, 256, 68096>>>();
    conv2_kernel<<<512, 256, 90624>>>();
    gemmout_kernel<<<256, 256, 53504>>>(w_out, out);
}